// round 11
// baseline (speedup 1.0000x reference)
#include <cuda_runtime.h>

#define KTAGS 48
#define PF 6
#define L2E 1.4426950408889634f
#define LN2 0.6931471805599453f

#define MAXB 4096
__device__ float g_wf[MAXB * KTAGS];
__device__ float g_wb[MAXB * KTAGS];
__device__ float g_c2f[MAXB];
__device__ float g_c2b[MAXB];
__device__ float g_path[MAXB];
__device__ float g_partial[64];

__device__ __forceinline__ unsigned long long pk2(float lo, float hi) {
    unsigned long long r;
    asm("mov.b64 %0,{%1,%2};" : "=l"(r) : "f"(lo), "f"(hi));
    return r;
}
__device__ __forceinline__ void unpk2(unsigned long long v, float& a, float& b) {
    asm("mov.b64 {%0,%1},%2;" : "=f"(a), "=f"(b) : "l"(v));
}
__device__ __forceinline__ unsigned long long ffma2(unsigned long long a, unsigned long long b,
                                                    unsigned long long c) {
    unsigned long long d;
    asm("fma.rn.f32x2 %0,%1,%2,%3;" : "=l"(d) : "l"(a), "l"(b), "l"(c));
    return d;
}
__device__ __forceinline__ unsigned long long fadd2(unsigned long long a, unsigned long long b) {
    unsigned long long d;
    asm("add.rn.f32x2 %0,%1,%2;" : "=l"(d) : "l"(a), "l"(b));
    return d;
}
__device__ __forceinline__ float ex2f(float x) {
    float r; asm("ex2.approx.f32 %0,%1;" : "=f"(r) : "f"(x)); return r;
}
__device__ __forceinline__ float lg2f(float x) {
    float r; asm("lg2.approx.f32 %0,%1;" : "=f"(r) : "f"(x)); return r;
}
__device__ __forceinline__ float rcpf(float x) {
    float r; asm("rcp.approx.f32 %0,%1;" : "=f"(r) : "f"(x)); return r;
}

// 3-row matvec: o_r = dot(E_r, svp[0..47]) for this lane's three rows.
__device__ __forceinline__ void matvec3(const unsigned long long* E0,
                                        const unsigned long long* E1,
                                        const unsigned long long* E2,
                                        const float* svp,
                                        float& o0, float& o1, float& o2) {
    const ulonglong2* vv = (const ulonglong2*)svp;
    unsigned long long z = pk2(0.0f, 0.0f);
    unsigned long long a0 = z, a1 = z, a2 = z, a3 = z;
    unsigned long long b0 = z, b1 = z, b2 = z, b3 = z;
    unsigned long long c0 = z, c1 = z, c2 = z, c3 = z;
#pragma unroll
    for (int q = 0; q < 12; q += 2) {
        ulonglong2 x0 = vv[q];
        ulonglong2 x1 = vv[q + 1];
        a0 = ffma2(E0[2 * q],     x0.x, a0);
        b0 = ffma2(E1[2 * q],     x0.x, b0);
        c0 = ffma2(E2[2 * q],     x0.x, c0);
        a1 = ffma2(E0[2 * q + 1], x0.y, a1);
        b1 = ffma2(E1[2 * q + 1], x0.y, b1);
        c1 = ffma2(E2[2 * q + 1], x0.y, c1);
        a2 = ffma2(E0[2 * q + 2], x1.x, a2);
        b2 = ffma2(E1[2 * q + 2], x1.x, b2);
        c2 = ffma2(E2[2 * q + 2], x1.x, c2);
        a3 = ffma2(E0[2 * q + 3], x1.y, a3);
        b3 = ffma2(E1[2 * q + 3], x1.y, b3);
        c3 = ffma2(E2[2 * q + 3], x1.y, c3);
    }
    unsigned long long sA = fadd2(fadd2(a0, a1), fadd2(a2, a3));
    unsigned long long sB = fadd2(fadd2(b0, b1), fadd2(b2, b3));
    unsigned long long sC = fadd2(fadd2(c0, c1), fadd2(c2, c3));
    float lo, hi;
    unpk2(sA, lo, hi); o0 = lo + hi;
    unpk2(sB, lo, hi); o1 = lo + hi;
    unpk2(sC, lo, hi); o2 = lo + hi;
}

// Bidirectional CRF, 2 batches per single-warp CTA via lane-group SIMD:
// lanes 0-15 = batch b0, lanes 16-31 = batch b1; each lane owns rows
// {jj, jj+16, jj+32} of its batch. CTAs [0,B/2): forward alpha 0..m;
// CTAs [B/2,B): backward beta L-1..m. Linear domain, renorm via lane-group
// shfl, off-chain C2 += lg2(r). sv padded to 56 floats so the two groups'
// buffers land in disjoint bank halves.
__global__ void __launch_bounds__(32) crf_bidir(
    const float* __restrict__ emis,   // [B, T, K]
    const int* __restrict__ lengths,  // [B]
    const int* __restrict__ tags,     // [B, T]
    const float* __restrict__ prior,  // [K]
    const float* __restrict__ trans,  // [K, K]
    const float* __restrict__ ftrans, // [K]
    int B2, int T)
{
    __shared__ __align__(16) float sv[2][2][56];  // [group][pingpong][48 used]

    const bool fwd = (blockIdx.x < (unsigned)B2);
    const int pairid = fwd ? blockIdx.x : (blockIdx.x - B2);
    const int b0i = 2 * pairid, b1i = b0i + 1;
    const int j = threadIdx.x;
    const int g = j >> 4;
    const int jj = j & 15;
    const int r0 = jj, r1 = jj + 16, r2 = jj + 32;
    const int gsrc = g << 4;

    int L0 = lengths[b0i]; L0 = L0 < 1 ? 1 : (L0 > T ? T : L0);
    int L1 = lengths[b1i]; L1 = L1 < 1 ? 1 : (L1 > T ? T : L1);

    const int bg = g ? b1i : b0i;
    const int Lg = g ? L1 : L0;
    const int mg = Lg >> 1;
    const float* ebg = emis + (size_t)bg * T * KTAGS;

    // Per-lane E rows (3 rows x 24 f32x2).
    unsigned long long E0[24], E1[24], E2[24];
    if (fwd) {
        const float4* t0 = (const float4*)(trans + r0 * KTAGS);
        const float4* t1 = (const float4*)(trans + r1 * KTAGS);
        const float4* t2 = (const float4*)(trans + r2 * KTAGS);
#pragma unroll
        for (int q = 0; q < 12; q++) {
            float4 v0 = t0[q], v1 = t1[q], v2 = t2[q];
            E0[2 * q]     = pk2(ex2f(v0.x * L2E), ex2f(v0.y * L2E));
            E0[2 * q + 1] = pk2(ex2f(v0.z * L2E), ex2f(v0.w * L2E));
            E1[2 * q]     = pk2(ex2f(v1.x * L2E), ex2f(v1.y * L2E));
            E1[2 * q + 1] = pk2(ex2f(v1.z * L2E), ex2f(v1.w * L2E));
            E2[2 * q]     = pk2(ex2f(v2.x * L2E), ex2f(v2.y * L2E));
            E2[2 * q + 1] = pk2(ex2f(v2.z * L2E), ex2f(v2.w * L2E));
        }
    } else {
#pragma unroll
        for (int q = 0; q < 24; q++) {
            int k0 = 2 * q, k1 = 2 * q + 1;
            E0[q] = pk2(ex2f(trans[k0 * KTAGS + r0] * L2E), ex2f(trans[k1 * KTAGS + r0] * L2E));
            E1[q] = pk2(ex2f(trans[k0 * KTAGS + r1] * L2E), ex2f(trans[k1 * KTAGS + r1] * L2E));
            E2[q] = pk2(ex2f(trans[k0 * KTAGS + r2] * L2E), ex2f(trans[k1 * KTAGS + r2] * L2E));
        }
    }

    if (fwd) {
        // ---------- forward alpha 0..m ----------
        float a0 = ebg[r0] + prior[r0];
        float a1 = ebg[r1] + prior[r1];
        float a2 = ebg[r2] + prior[r2];
        float m0v = __shfl_sync(0xffffffffu, a0, gsrc);
        float C2 = m0v * L2E;
        float w0 = ex2f((a0 - m0v) * L2E);
        float w1 = ex2f((a1 - m0v) * L2E);
        float w2 = ex2f((a2 - m0v) * L2E);
        sv[g][0][r0] = w0; sv[g][0][r1] = w1; sv[g][0][r2] = w2;
        __syncwarp();
        int p = 0;

        const int Lf = mg + 1;                       // own (lane-group) bound
        const int Lf0 = (L0 >> 1) + 1, Lf1 = (L1 >> 1) + 1;
        const int Lfmin = Lf0 < Lf1 ? Lf0 : Lf1;
        const int Lfmax = Lf0 > Lf1 ? Lf0 : Lf1;

        float raw0[PF], raw1[PF], raw2[PF];
#pragma unroll
        for (int d = 0; d < PF; d++) {
            int t = 1 + d;
            bool ok = t < Lf;
            size_t off = (size_t)t * KTAGS;
            raw0[d] = ok ? ebg[off + r0] : 0.0f;
            raw1[d] = ok ? ebg[off + r1] : 0.0f;
            raw2[d] = ok ? ebg[off + r2] : 0.0f;
        }

        int t0 = 1;
        // phase 1: branch-free while both groups fully in-range
        {
            const float* bp = ebg + (size_t)(1 + PF) * KTAGS + r0;
            for (; t0 + 2 * PF <= Lfmin; t0 += PF) {
#pragma unroll
                for (int d = 0; d < PF; d++) {
                    float e0 = ex2f(raw0[d] * L2E);
                    float e1 = ex2f(raw1[d] * L2E);
                    float e2 = ex2f(raw2[d] * L2E);
                    raw0[d] = bp[d * KTAGS];
                    raw1[d] = bp[d * KTAGS + 16];
                    raw2[d] = bp[d * KTAGS + 32];

                    float q0, q1, q2;
                    if ((d & 3) == 0) {
                        float r = __shfl_sync(0xffffffffu, w0, gsrc);
                        float rr = rcpf(r);
                        C2 += lg2f(r);
                        q0 = e0 * rr; q1 = e1 * rr; q2 = e2 * rr;
                    } else {
                        q0 = e0; q1 = e1; q2 = e2;
                    }

                    float u0, u1, u2;
                    matvec3(E0, E1, E2, sv[g][p], u0, u1, u2);
                    w0 = u0 * q0; w1 = u1 * q1; w2 = u2 * q2;

                    const int pn = p ^ 1;
                    sv[g][pn][r0] = w0; sv[g][pn][r1] = w1; sv[g][pn][r2] = w2;
                    __syncwarp();
                    p = pn;
                }
                bp += PF * KTAGS;
            }
        }
        // phase 2: predicated tail until the longer group finishes
        for (; t0 < Lfmax; t0 += PF) {
#pragma unroll
            for (int d = 0; d < PF; d++) {
                const int t = t0 + d;
                if (t >= Lfmax) break;
                const bool act = t < Lf;

                float e0 = ex2f(raw0[d] * L2E);
                float e1 = ex2f(raw1[d] * L2E);
                float e2 = ex2f(raw2[d] * L2E);
                {
                    int tn = t + PF;
                    bool ok = tn < Lf;
                    size_t off = (size_t)tn * KTAGS;
                    raw0[d] = ok ? ebg[off + r0] : 0.0f;
                    raw1[d] = ok ? ebg[off + r1] : 0.0f;
                    raw2[d] = ok ? ebg[off + r2] : 0.0f;
                }

                float q0, q1, q2;
                if ((d & 3) == 0) {
                    float r = __shfl_sync(0xffffffffu, w0, gsrc);
                    float rr = rcpf(r);
                    C2 += act ? lg2f(r) : 0.0f;
                    q0 = e0 * rr; q1 = e1 * rr; q2 = e2 * rr;
                } else {
                    q0 = e0; q1 = e1; q2 = e2;
                }

                float u0, u1, u2;
                matvec3(E0, E1, E2, sv[g][p], u0, u1, u2);
                w0 = act ? u0 * q0 : w0;
                w1 = act ? u1 * q1 : w1;
                w2 = act ? u2 * q2 : w2;

                const int pn = p ^ 1;
                sv[g][pn][r0] = w0; sv[g][pn][r1] = w1; sv[g][pn][r2] = w2;
                __syncwarp();
                p = pn;
            }
        }

        g_wf[bg * KTAGS + r0] = w0;
        g_wf[bg * KTAGS + r1] = w1;
        g_wf[bg * KTAGS + r2] = w2;
        if (jj == 0) g_c2f[bg] = C2;

        // ---- path scores: two full-warp loops (b0 then b1) ----
#pragma unroll
        for (int which = 0; which < 2; which++) {
            const int bb = which ? b1i : b0i;
            const int LL = which ? L1 : L0;
            const float* eb = emis + (size_t)bb * T * KTAGS;
            const int* tb = tags + (size_t)bb * T;
            float acc = 0.0f;
            for (int t = j; t < LL; t += 32) {
                int tg = min(max(tb[t], 0), KTAGS - 1);
                float tr = (t == 0) ? prior[tg]
                                    : trans[tg * KTAGS + min(max(tb[t - 1], 0), KTAGS - 1)];
                acc += eb[(size_t)t * KTAGS + tg] + tr;
            }
#pragma unroll
            for (int s = 16; s > 0; s >>= 1)
                acc += __shfl_xor_sync(0xffffffffu, acc, s);
            if (j == 0)
                g_path[bb] = acc + ftrans[min(max(tb[LL - 1], 0), KTAGS - 1)];
        }
    } else {
        // ---------- backward beta L-1..m ----------
        float ef0 = ex2f(ftrans[r0] * L2E);
        float ef1 = ex2f(ftrans[r1] * L2E);
        float ef2 = ex2f(ftrans[r2] * L2E);

        const int nb = Lg - 1 - mg;                 // own steps (>=0)
        const int nf = nb > 0 ? nb - 1 : 0;         // full steps
        const int nbc0 = L0 - 1 - (L0 >> 1), nbc1 = L1 - 1 - (L1 >> 1);
        const int nf0 = nbc0 > 0 ? nbc0 - 1 : 0;
        const int nf1 = nbc1 > 0 ? nbc1 - 1 : 0;
        const int nfmin = nf0 < nf1 ? nf0 : nf1;
        const int nfmax = nf0 > nf1 ? nf0 : nf1;

        float z0, z1, z2;
        {
            size_t off = (size_t)(Lg - 1) * KTAGS;
            float q0 = ebg[off + r0], q1 = ebg[off + r1], q2 = ebg[off + r2];
            z0 = (nb >= 1) ? ex2f((ftrans[r0] + q0) * L2E) : ef0;
            z1 = (nb >= 1) ? ex2f((ftrans[r1] + q1) * L2E) : ef1;
            z2 = (nb >= 1) ? ex2f((ftrans[r2] + q2) * L2E) : ef2;
        }
        float C2 = 0.0f;
        int p = 0;

        float raw0[PF], raw1[PF], raw2[PF];
#pragma unroll
        for (int d = 0; d < PF; d++) {
            bool ok = d < nf;
            int tt = Lg - 2 - d; tt = tt < 0 ? 0 : tt;
            size_t off = (size_t)tt * KTAGS;
            raw0[d] = ok ? ebg[off + r0] : 0.0f;
            raw1[d] = ok ? ebg[off + r1] : 0.0f;
            raw2[d] = ok ? ebg[off + r2] : 0.0f;
        }

        int s0 = 0;
        // phase 1: branch-free while both groups in-range
        {
            int bb = Lg - 2 - PF; bb = bb < 0 ? 0 : bb;
            const float* bq = ebg + (size_t)bb * KTAGS + r0;
            for (; s0 + 2 * PF <= nfmin; s0 += PF) {
#pragma unroll
                for (int d = 0; d < PF; d++) {
                    float e0 = ex2f(raw0[d] * L2E);
                    float e1 = ex2f(raw1[d] * L2E);
                    float e2 = ex2f(raw2[d] * L2E);
                    raw0[d] = *(bq - d * KTAGS);
                    raw1[d] = *(bq - d * KTAGS + 16);
                    raw2[d] = *(bq - d * KTAGS + 32);

                    float q0, q1, q2;
                    if ((d & 3) == 0) {
                        float r = __shfl_sync(0xffffffffu, z0, gsrc);
                        float rr = rcpf(r);
                        C2 += lg2f(r);
                        q0 = e0 * rr; q1 = e1 * rr; q2 = e2 * rr;
                    } else {
                        q0 = e0; q1 = e1; q2 = e2;
                    }

                    const int pn = p ^ 1;
                    sv[g][pn][r0] = z0 * q0;
                    sv[g][pn][r1] = z1 * q1;
                    sv[g][pn][r2] = z2 * q2;
                    __syncwarp();
                    float u0, u1, u2;
                    matvec3(E0, E1, E2, sv[g][pn], u0, u1, u2);
                    z0 = u0; z1 = u1; z2 = u2;
                    p = pn;
                }
                bq -= PF * KTAGS;
            }
        }
        // phase 2: predicated tail
        for (; s0 < nfmax; s0 += PF) {
#pragma unroll
            for (int d = 0; d < PF; d++) {
                const int s = s0 + d;
                if (s >= nfmax) break;
                const bool act = s < nf;

                float e0 = ex2f(raw0[d] * L2E);
                float e1 = ex2f(raw1[d] * L2E);
                float e2 = ex2f(raw2[d] * L2E);
                {
                    int sn = s + PF;
                    bool ok = sn < nf;
                    int tt = Lg - 2 - sn; tt = tt < 0 ? 0 : tt;
                    size_t off = (size_t)tt * KTAGS;
                    raw0[d] = ok ? ebg[off + r0] : 0.0f;
                    raw1[d] = ok ? ebg[off + r1] : 0.0f;
                    raw2[d] = ok ? ebg[off + r2] : 0.0f;
                }

                float q0, q1, q2;
                if ((d & 3) == 0) {
                    float r = __shfl_sync(0xffffffffu, z0, gsrc);
                    float rr = rcpf(r);
                    C2 += act ? lg2f(r) : 0.0f;
                    q0 = e0 * rr; q1 = e1 * rr; q2 = e2 * rr;
                } else {
                    q0 = e0; q1 = e1; q2 = e2;
                }

                const int pn = p ^ 1;
                sv[g][pn][r0] = act ? z0 * q0 : z0;
                sv[g][pn][r1] = act ? z1 * q1 : z1;
                sv[g][pn][r2] = act ? z2 * q2 : z2;
                __syncwarp();
                float u0, u1, u2;
                matvec3(E0, E1, E2, sv[g][pn], u0, u1, u2);
                z0 = act ? u0 : z0;
                z1 = act ? u1 : z1;
                z2 = act ? u2 : z2;
                p = pn;
            }
        }
        // final matvec-only step (operand = raw z, no emission)
        {
            const int pn = p ^ 1;
            sv[g][pn][r0] = z0; sv[g][pn][r1] = z1; sv[g][pn][r2] = z2;
            __syncwarp();
            float u0, u1, u2;
            matvec3(E0, E1, E2, sv[g][pn], u0, u1, u2);
            z0 = (nb >= 1) ? u0 : ef0;
            z1 = (nb >= 1) ? u1 : ef1;
            z2 = (nb >= 1) ? u2 : ef2;
        }

        g_wb[bg * KTAGS + r0] = z0;
        g_wb[bg * KTAGS + r1] = z1;
        g_wb[bg * KTAGS + r2] = z2;
        if (jj == 0) g_c2b[bg] = C2;
    }
}

// Parallel combine: 32 blocks x 256 threads, one warp per batch iteration.
__global__ void crf_combine(int B) {
    __shared__ float sh[8];
    const int tid = threadIdx.x;
    const int wid = tid >> 5, j = tid & 31;
    const int gw = blockIdx.x * 8 + wid;
    float v = 0.0f;
    for (int b = gw; b < B; b += 256) {
        float d = g_wf[b * KTAGS + j] * g_wb[b * KTAGS + j];
        if (j < 16) d += g_wf[b * KTAGS + 32 + j] * g_wb[b * KTAGS + 32 + j];
#pragma unroll
        for (int s = 16; s > 0; s >>= 1) d += __shfl_xor_sync(0xffffffffu, d, s);
        if (j == 0)
            v += (lg2f(d) + g_c2f[b] + g_c2b[b]) * LN2 - g_path[b];
    }
    if (j == 0) sh[wid] = v;
    __syncthreads();
    if (tid == 0) {
        float s = 0.0f;
#pragma unroll
        for (int k = 0; k < 8; k++) s += sh[k];
        g_partial[blockIdx.x] = s;
    }
}

__global__ void crf_final(float* __restrict__ out, int B) {
    const int j = threadIdx.x;
    float v = g_partial[j];
#pragma unroll
    for (int s = 16; s > 0; s >>= 1) v += __shfl_xor_sync(0xffffffffu, v, s);
    if (j == 0) out[0] = v / (float)B;
}

extern "C" void kernel_launch(void* const* d_in, const int* in_sizes, int n_in,
                              void* d_out, int out_size) {
    const float* emis    = (const float*)d_in[0];
    const int*   lengths = (const int*)d_in[1];
    const int*   tags    = (const int*)d_in[2];
    const float* prior   = (const float*)d_in[3];
    const float* trans   = (const float*)d_in[4];
    const float* ftrans  = (const float*)d_in[5];

    const int B = in_sizes[1];              // lengths count
    const int T = in_sizes[2] / B;          // tags = [B, T]

    crf_bidir<<<B, 32>>>(emis, lengths, tags, prior, trans, ftrans, B / 2, T);
    crf_combine<<<32, 256>>>(B);
    crf_final<<<1, 32>>>((float*)d_out, B);
}

// round 12
// speedup vs baseline: 1.7988x; 1.7988x over previous
#include <cuda_runtime.h>

#define KTAGS 48
#define PF 8
#define L2E 1.4426950408889634f
#define LN2 0.6931471805599453f

#define MAXB 4096
__device__ float g_wf[MAXB * KTAGS];
__device__ float g_wb[MAXB * KTAGS];
__device__ float g_c2f[MAXB];
__device__ float g_c2b[MAXB];
__device__ float g_path[MAXB];
__device__ float g_partial[64];
__device__ int   g_perm[MAXB];

__device__ __forceinline__ unsigned long long pk2(float lo, float hi) {
    unsigned long long r;
    asm("mov.b64 %0,{%1,%2};" : "=l"(r) : "f"(lo), "f"(hi));
    return r;
}
__device__ __forceinline__ void unpk2(unsigned long long v, float& a, float& b) {
    asm("mov.b64 {%0,%1},%2;" : "=f"(a), "=f"(b) : "l"(v));
}
__device__ __forceinline__ unsigned long long ffma2(unsigned long long a, unsigned long long b,
                                                    unsigned long long c) {
    unsigned long long d;
    asm("fma.rn.f32x2 %0,%1,%2,%3;" : "=l"(d) : "l"(a), "l"(b), "l"(c));
    return d;
}
__device__ __forceinline__ unsigned long long fadd2(unsigned long long a, unsigned long long b) {
    unsigned long long d;
    asm("add.rn.f32x2 %0,%1,%2;" : "=l"(d) : "l"(a), "l"(b));
    return d;
}
__device__ __forceinline__ float ex2f(float x) {
    float r; asm("ex2.approx.f32 %0,%1;" : "=f"(r) : "f"(x)); return r;
}
__device__ __forceinline__ float lg2f(float x) {
    float r; asm("lg2.approx.f32 %0,%1;" : "=f"(r) : "f"(x)); return r;
}
__device__ __forceinline__ float rcpf(float x) {
    float r; asm("rcp.approx.f32 %0,%1;" : "=f"(r) : "f"(x)); return r;
}

__device__ __forceinline__ void matvec48(const unsigned long long* MA,
                                         const unsigned long long* MB,
                                         const float* svp,
                                         float& outA, float& outB) {
    const ulonglong2* vv = (const ulonglong2*)svp;
    unsigned long long a0 = pk2(0.0f, 0.0f), a1 = a0, a2 = a0, a3 = a0;
    unsigned long long b0 = a0, b1 = a0, b2 = a0, b3 = a0;
#pragma unroll
    for (int q = 0; q < 12; q += 2) {
        ulonglong2 x0 = vv[q];
        ulonglong2 x1 = vv[q + 1];
        a0 = ffma2(MA[2 * q],     x0.x, a0);
        b0 = ffma2(MB[2 * q],     x0.x, b0);
        a1 = ffma2(MA[2 * q + 1], x0.y, a1);
        b1 = ffma2(MB[2 * q + 1], x0.y, b1);
        a2 = ffma2(MA[2 * q + 2], x1.x, a2);
        b2 = ffma2(MB[2 * q + 2], x1.x, b2);
        a3 = ffma2(MA[2 * q + 3], x1.y, a3);
        b3 = ffma2(MB[2 * q + 3], x1.y, b3);
    }
    unsigned long long sA = fadd2(fadd2(a0, a1), fadd2(a2, a3));
    unsigned long long sB = fadd2(fadd2(b0, b1), fadd2(b2, b3));
    float alo, ahi, blo, bhi;
    unpk2(sA, alo, ahi);
    unpk2(sB, blo, bhi);
    outA = alo + ahi;
    outB = blo + bhi;
}

// Sort batch indices by DESCENDING length (bitonic, in smem). perm[rank]=b.
// With the contiguous-modular bid->SM map, ranks stripe across SMs so each SM
// gets chains from every length stratum -> balanced tail.
__global__ void crf_sort(const int* __restrict__ lengths, int B, int T) {
    __shared__ unsigned key[MAXB];
    int np2 = 1;
    while (np2 < B) np2 <<= 1;
    for (int k = threadIdx.x; k < np2; k += blockDim.x) {
        unsigned kv = 0;
        if (k < B) {
            int L = lengths[k];
            L = L < 1 ? 1 : (L > T ? T : L);
            kv = ((unsigned)L << 16) | (unsigned)k;
        }
        key[k] = kv;
    }
    __syncthreads();
    for (int kk = 2; kk <= np2; kk <<= 1) {
        for (int jj = kk >> 1; jj > 0; jj >>= 1) {
            for (int t = threadIdx.x; t < np2; t += blockDim.x) {
                int ixj = t ^ jj;
                if (ixj > t) {
                    bool dir = (t & kk) == 0;   // descending overall
                    unsigned a = key[t], b2 = key[ixj];
                    if ((a < b2) == dir) { key[t] = b2; key[ixj] = a; }
                }
            }
            __syncthreads();
        }
    }
    for (int k = threadIdx.x; k < B; k += blockDim.x)
        g_perm[k] = (int)(key[k] & 0xffffu);
}

// Bidirectional CRF: CTA 2i = forward alpha 0..m of batch perm[i];
// CTA 2i+1 = backward beta L-1..m. Single warp per CTA; syncwarp per step;
// linear domain; renorm every 4th step; branch-free PF-block hot loop.
__global__ void __launch_bounds__(32) crf_bidir(
    const float* __restrict__ emis,   // [B, T, K]
    const int* __restrict__ lengths,  // [B]
    const int* __restrict__ tags,     // [B, T]
    const float* __restrict__ prior,  // [K]
    const float* __restrict__ trans,  // [K, K]
    const float* __restrict__ ftrans, // [K]
    int B, int T)
{
    __shared__ __align__(16) float sv[2][KTAGS];

    const bool fwd = (blockIdx.x & 1u) == 0u;
    const int b = g_perm[blockIdx.x >> 1];
    const int j = threadIdx.x;
    const bool hB = (j < 16);
    const int rA = j;
    const int rB = 32 + (j & 15);

    int L = lengths[b];
    if (L < 1) L = 1;
    if (L > T) L = T;
    const int m = L >> 1;

    const float* eb = emis + (size_t)b * T * KTAGS;

    if (fwd) {
        unsigned long long EA[24], EB[24];
        {
            const float4* trA = (const float4*)(trans + rA * KTAGS);
            const float4* trB = (const float4*)(trans + rB * KTAGS);
#pragma unroll
            for (int q = 0; q < 12; q++) {
                float4 va = trA[q];
                EA[2 * q]     = pk2(ex2f(va.x * L2E), ex2f(va.y * L2E));
                EA[2 * q + 1] = pk2(ex2f(va.z * L2E), ex2f(va.w * L2E));
                float4 vb4 = trB[q];
                EB[2 * q]     = pk2(ex2f(vb4.x * L2E), ex2f(vb4.y * L2E));
                EB[2 * q + 1] = pk2(ex2f(vb4.z * L2E), ex2f(vb4.w * L2E));
            }
        }

        float aA = eb[rA] + prior[rA];
        float aB = eb[rB] + prior[rB];
        float m0 = __shfl_sync(0xffffffffu, aA, 0);
        float C2 = m0 * L2E;
        float wA = ex2f((aA - m0) * L2E);
        float wB = ex2f((aB - m0) * L2E);
        sv[0][rA] = wA;
        if (hB) sv[0][rB] = wB;
        __syncwarp();
        int p = 0;

        const int Lf = m + 1;   // consume t = 1..m
        float rawA[PF], rawB[PF];
#pragma unroll
        for (int d = 0; d < PF; d++) {
            int t = 1 + d;
            rawA[d] = (t < Lf) ? eb[(size_t)t * KTAGS + rA] : 0.0f;
            rawB[d] = (t < Lf) ? eb[(size_t)t * KTAGS + rB] : 0.0f;
        }

        int t0 = 1;
        // ---- phase 1: branch-free full blocks (all refills in-range) ----
        {
            const float* bA = eb + (size_t)(1 + PF) * KTAGS + rA;
            const float* bBp = eb + (size_t)(1 + PF) * KTAGS + rB;
            for (; t0 + 2 * PF <= Lf; t0 += PF) {
#pragma unroll
                for (int d = 0; d < PF; d++) {
                    float eetA = ex2f(rawA[d] * L2E);
                    float eetB = ex2f(rawB[d] * L2E);
                    rawA[d] = bA[d * KTAGS];
                    rawB[d] = bBp[d * KTAGS];

                    float gA = eetA, gB = eetB;
                    if ((d & 3) == 0) {
                        float r = __shfl_sync(0xffffffffu, wA, 0);
                        float rr = rcpf(r);
                        C2 += lg2f(r);
                        gA = eetA * rr;
                        gB = eetB * rr;
                    }

                    float uA, uB;
                    matvec48(EA, EB, sv[p], uA, uB);
                    wA = uA * gA;
                    wB = uB * gB;

                    const int q2 = p ^ 1;
                    sv[q2][rA] = wA;
                    if (hB) sv[q2][rB] = wB;
                    __syncwarp();
                    p = q2;
                }
                bA += PF * KTAGS;
                bBp += PF * KTAGS;
            }
        }
        // ---- phase 2: predicated tail ----
        for (; t0 < Lf; t0 += PF) {
#pragma unroll
            for (int d = 0; d < PF; d++) {
                const int t = t0 + d;
                if (t >= Lf) break;

                float eetA = ex2f(rawA[d] * L2E);
                float eetB = ex2f(rawB[d] * L2E);
                {
                    int tn = t + PF;
                    rawA[d] = (tn < Lf) ? eb[(size_t)tn * KTAGS + rA] : 0.0f;
                    rawB[d] = (tn < Lf) ? eb[(size_t)tn * KTAGS + rB] : 0.0f;
                }

                float gA = eetA, gB = eetB;
                if ((d & 3) == 0) {
                    float r = __shfl_sync(0xffffffffu, wA, 0);
                    float rr = rcpf(r);
                    C2 += lg2f(r);
                    gA = eetA * rr;
                    gB = eetB * rr;
                }

                float uA, uB;
                matvec48(EA, EB, sv[p], uA, uB);
                wA = uA * gA;
                wB = uB * gB;

                const int q2 = p ^ 1;
                sv[q2][rA] = wA;
                if (hB) sv[q2][rB] = wB;
                __syncwarp();
                p = q2;
            }
        }

        g_wf[b * KTAGS + rA] = wA;
        if (hB) g_wf[b * KTAGS + rB] = wB;
        if (j == 0) g_c2f[b] = C2;

        // ---- path score over full L ----
        const int* tb = tags + (size_t)b * T;
        float acc = 0.0f;
        for (int t = j; t < L; t += 32) {
            int tg = min(max(tb[t], 0), KTAGS - 1);
            float tr = (t == 0) ? prior[tg]
                                : trans[tg * KTAGS + min(max(tb[t - 1], 0), KTAGS - 1)];
            acc += eb[(size_t)t * KTAGS + tg] + tr;
        }
#pragma unroll
        for (int s = 16; s > 0; s >>= 1)
            acc += __shfl_xor_sync(0xffffffffu, acc, s);
        if (j == 0)
            g_path[b] = acc + ftrans[min(max(tb[L - 1], 0), KTAGS - 1)];
    } else {
        // Backward: beta_t = E^T (exp(e_{t+1}) . beta_{t+1})
        unsigned long long EA[24], EB[24];
#pragma unroll
        for (int q = 0; q < 24; q++) {
            int j0 = 2 * q, j1 = 2 * q + 1;
            EA[q] = pk2(ex2f(trans[j0 * KTAGS + rA] * L2E),
                        ex2f(trans[j1 * KTAGS + rA] * L2E));
            EB[q] = pk2(ex2f(trans[j0 * KTAGS + rB] * L2E),
                        ex2f(trans[j1 * KTAGS + rB] * L2E));
        }

        float C2 = 0.0f;
        float vbA, vbB;

        if (m == L - 1) {
            vbA = ex2f(ftrans[rA] * L2E);
            vbB = ex2f(ftrans[rB] * L2E);
        } else {
            float zA = ex2f((ftrans[rA] + eb[(size_t)(L - 1) * KTAGS + rA]) * L2E);
            float zB = ex2f((ftrans[rB] + eb[(size_t)(L - 1) * KTAGS + rB]) * L2E);
            int p = 0;

            const int nsteps = L - 1 - m;
            const int nfull = nsteps - 1;

            float rawA[PF], rawB[PF];
#pragma unroll
            for (int d = 0; d < PF; d++) {
                int t = L - 2 - d;
                rawA[d] = (d < nfull) ? eb[(size_t)t * KTAGS + rA] : 0.0f;
                rawB[d] = (d < nfull) ? eb[(size_t)t * KTAGS + rB] : 0.0f;
            }

            int s0 = 0;
            // ---- phase 1: branch-free full blocks ----
            if (2 * PF <= nfull) {
                const float* bA = eb + (size_t)(L - 2 - PF) * KTAGS + rA;
                const float* bBp = eb + (size_t)(L - 2 - PF) * KTAGS + rB;
                for (; s0 + 2 * PF <= nfull; s0 += PF) {
#pragma unroll
                    for (int d = 0; d < PF; d++) {
                        float eetA = ex2f(rawA[d] * L2E);
                        float eetB = ex2f(rawB[d] * L2E);
                        rawA[d] = *(bA - d * KTAGS);
                        rawB[d] = *(bBp - d * KTAGS);

                        float gA = eetA, gB = eetB;
                        if ((d & 3) == 0) {
                            float r = __shfl_sync(0xffffffffu, zA, 0);
                            float rr = rcpf(r);
                            C2 += lg2f(r);
                            gA = eetA * rr;
                            gB = eetB * rr;
                        }

                        sv[p ^ 1][rA] = zA * gA;
                        if (hB) sv[p ^ 1][rB] = zB * gB;
                        __syncwarp();
                        float uA, uB;
                        matvec48(EA, EB, sv[p ^ 1], uA, uB);
                        zA = uA;
                        zB = uB;
                        p ^= 1;
                    }
                    bA -= PF * KTAGS;
                    bBp -= PF * KTAGS;
                }
            }
            // ---- phase 2: predicated tail ----
            for (; s0 < nfull; s0 += PF) {
#pragma unroll
                for (int d = 0; d < PF; d++) {
                    const int s = s0 + d;
                    if (s >= nfull) break;
                    const int t = L - 2 - s;

                    float eetA = ex2f(rawA[d] * L2E);
                    float eetB = ex2f(rawB[d] * L2E);
                    {
                        int sn = s + PF;
                        int tn = t - PF;
                        rawA[d] = (sn < nfull) ? eb[(size_t)tn * KTAGS + rA] : 0.0f;
                        rawB[d] = (sn < nfull) ? eb[(size_t)tn * KTAGS + rB] : 0.0f;
                    }

                    float gA = eetA, gB = eetB;
                    if ((d & 3) == 0) {
                        float r = __shfl_sync(0xffffffffu, zA, 0);
                        float rr = rcpf(r);
                        C2 += lg2f(r);
                        gA = eetA * rr;
                        gB = eetB * rr;
                    }

                    sv[p ^ 1][rA] = zA * gA;
                    if (hB) sv[p ^ 1][rB] = zB * gB;
                    __syncwarp();
                    float uA, uB;
                    matvec48(EA, EB, sv[p ^ 1], uA, uB);
                    zA = uA;
                    zB = uB;
                    p ^= 1;
                }
            }
            // Final step (t = m): matvec only — operand is raw z (no emission).
            sv[p ^ 1][rA] = zA;
            if (hB) sv[p ^ 1][rB] = zB;
            __syncwarp();
            matvec48(EA, EB, sv[p ^ 1], vbA, vbB);
        }

        g_wb[b * KTAGS + rA] = vbA;
        if (hB) g_wb[b * KTAGS + rB] = vbB;
        if (j == 0) g_c2b[b] = C2;
    }
}

// Parallel combine: 32 blocks x 256 threads, one warp per batch iteration.
__global__ void crf_combine(int B) {
    __shared__ float sh[8];
    const int tid = threadIdx.x;
    const int wid = tid >> 5, j = tid & 31;
    const int gw = blockIdx.x * 8 + wid;
    float v = 0.0f;
    for (int b = gw; b < B; b += 256) {
        float d = g_wf[b * KTAGS + j] * g_wb[b * KTAGS + j];
        if (j < 16) d += g_wf[b * KTAGS + 32 + j] * g_wb[b * KTAGS + 32 + j];
#pragma unroll
        for (int s = 16; s > 0; s >>= 1) d += __shfl_xor_sync(0xffffffffu, d, s);
        if (j == 0)
            v += (lg2f(d) + g_c2f[b] + g_c2b[b]) * LN2 - g_path[b];
    }
    if (j == 0) sh[wid] = v;
    __syncthreads();
    if (tid == 0) {
        float s = 0.0f;
#pragma unroll
        for (int k = 0; k < 8; k++) s += sh[k];
        g_partial[blockIdx.x] = s;
    }
}

__global__ void crf_final(float* __restrict__ out, int B) {
    const int j = threadIdx.x;
    float v = g_partial[j];
#pragma unroll
    for (int s = 16; s > 0; s >>= 1) v += __shfl_xor_sync(0xffffffffu, v, s);
    if (j == 0) out[0] = v / (float)B;
}

extern "C" void kernel_launch(void* const* d_in, const int* in_sizes, int n_in,
                              void* d_out, int out_size) {
    const float* emis    = (const float*)d_in[0];
    const int*   lengths = (const int*)d_in[1];
    const int*   tags    = (const int*)d_in[2];
    const float* prior   = (const float*)d_in[3];
    const float* trans   = (const float*)d_in[4];
    const float* ftrans  = (const float*)d_in[5];

    const int B = in_sizes[1];              // lengths count
    const int T = in_sizes[2] / B;          // tags = [B, T]

    crf_sort<<<1, 512>>>(lengths, B, T);
    crf_bidir<<<2 * B, 32>>>(emis, lengths, tags, prior, trans, ftrans, B, T);
    crf_combine<<<32, 256>>>(B);
    crf_final<<<1, 32>>>((float*)d_out, B);
}

// round 13
// speedup vs baseline: 2.1406x; 1.1900x over previous
#include <cuda_runtime.h>

#define KTAGS 48
#define PF 8
#define L2E 1.4426950408889634f
#define LN2 0.6931471805599453f

#define MAXB 4096
__device__ float g_wf[MAXB * KTAGS];
__device__ float g_wb[MAXB * KTAGS];
__device__ float g_c2f[MAXB];
__device__ float g_c2b[MAXB];
__device__ float g_path[MAXB];
__device__ float g_partial[64];
__device__ int   g_perm[MAXB];
__device__ unsigned g_done = 0;

__device__ __forceinline__ unsigned long long pk2(float lo, float hi) {
    unsigned long long r;
    asm("mov.b64 %0,{%1,%2};" : "=l"(r) : "f"(lo), "f"(hi));
    return r;
}
__device__ __forceinline__ void unpk2(unsigned long long v, float& a, float& b) {
    asm("mov.b64 {%0,%1},%2;" : "=f"(a), "=f"(b) : "l"(v));
}
__device__ __forceinline__ unsigned long long ffma2(unsigned long long a, unsigned long long b,
                                                    unsigned long long c) {
    unsigned long long d;
    asm("fma.rn.f32x2 %0,%1,%2,%3;" : "=l"(d) : "l"(a), "l"(b), "l"(c));
    return d;
}
__device__ __forceinline__ unsigned long long fadd2(unsigned long long a, unsigned long long b) {
    unsigned long long d;
    asm("add.rn.f32x2 %0,%1,%2;" : "=l"(d) : "l"(a), "l"(b));
    return d;
}
__device__ __forceinline__ float ex2f(float x) {
    float r; asm("ex2.approx.f32 %0,%1;" : "=f"(r) : "f"(x)); return r;
}
__device__ __forceinline__ float lg2f(float x) {
    float r; asm("lg2.approx.f32 %0,%1;" : "=f"(r) : "f"(x)); return r;
}
__device__ __forceinline__ float rcpf(float x) {
    float r; asm("rcp.approx.f32 %0,%1;" : "=f"(r) : "f"(x)); return r;
}

__device__ __forceinline__ void matvec48(const unsigned long long* MA,
                                         const unsigned long long* MB,
                                         const float* svp,
                                         float& outA, float& outB) {
    const ulonglong2* vv = (const ulonglong2*)svp;
    unsigned long long a0 = pk2(0.0f, 0.0f), a1 = a0, a2 = a0, a3 = a0;
    unsigned long long b0 = a0, b1 = a0, b2 = a0, b3 = a0;
#pragma unroll
    for (int q = 0; q < 12; q += 2) {
        ulonglong2 x0 = vv[q];
        ulonglong2 x1 = vv[q + 1];
        a0 = ffma2(MA[2 * q],     x0.x, a0);
        b0 = ffma2(MB[2 * q],     x0.x, b0);
        a1 = ffma2(MA[2 * q + 1], x0.y, a1);
        b1 = ffma2(MB[2 * q + 1], x0.y, b1);
        a2 = ffma2(MA[2 * q + 2], x1.x, a2);
        b2 = ffma2(MB[2 * q + 2], x1.x, b2);
        a3 = ffma2(MA[2 * q + 3], x1.y, a3);
        b3 = ffma2(MB[2 * q + 3], x1.y, b3);
    }
    unsigned long long sA = fadd2(fadd2(a0, a1), fadd2(a2, a3));
    unsigned long long sB = fadd2(fadd2(b0, b1), fadd2(b2, b3));
    float alo, ahi, blo, bhi;
    unpk2(sA, alo, ahi);
    unpk2(sB, blo, bhi);
    outA = alo + ahi;
    outB = blo + bhi;
}

// Sort batch indices by DESCENDING length (bitonic, in smem). perm[rank]=b.
__global__ void crf_sort(const int* __restrict__ lengths, int B, int T) {
    __shared__ unsigned key[MAXB];
    int np2 = 1;
    while (np2 < B) np2 <<= 1;
    for (int k = threadIdx.x; k < np2; k += blockDim.x) {
        unsigned kv = 0;
        if (k < B) {
            int L = lengths[k];
            L = L < 1 ? 1 : (L > T ? T : L);
            kv = ((unsigned)L << 16) | (unsigned)k;
        }
        key[k] = kv;
    }
    __syncthreads();
    for (int kk = 2; kk <= np2; kk <<= 1) {
        for (int jj = kk >> 1; jj > 0; jj >>= 1) {
            for (int t = threadIdx.x; t < np2; t += blockDim.x) {
                int ixj = t ^ jj;
                if (ixj > t) {
                    bool dir = (t & kk) == 0;   // descending overall
                    unsigned a = key[t], b2 = key[ixj];
                    if ((a < b2) == dir) { key[t] = b2; key[ixj] = a; }
                }
            }
            __syncthreads();
        }
    }
    for (int k = threadIdx.x; k < B; k += blockDim.x)
        g_perm[k] = (int)(key[k] & 0xffffu);
}

// Makespan-balanced bidirectional CRF: CTA i sequentially runs
//   phase 1: forward alpha 0..m of batch perm[i]        (~L_i/2 steps)
//   phase 2: backward beta L-1..m of batch perm[B-1-i]  (~L_{B-1-i}/2 steps)
// Since lengths are ~uniform, L_i + L_{B-1-i} ~ const, so every CTA does
// ~T/2 serial steps -> flat makespan at only 512 CTAs (~0.87 warps/SMSP).
__global__ void __launch_bounds__(32) crf_bidir(
    const float* __restrict__ emis,   // [B, T, K]
    const int* __restrict__ lengths,  // [B]
    const int* __restrict__ tags,     // [B, T]
    const float* __restrict__ prior,  // [K]
    const float* __restrict__ trans,  // [K, K]
    const float* __restrict__ ftrans, // [K]
    int B, int T)
{
    __shared__ __align__(16) float sv[2][KTAGS];

    const int j = threadIdx.x;
    const bool hB = (j < 16);
    const int rA = j;
    const int rB = 32 + (j & 15);

    // ================= phase 1: forward =================
    {
        const int b = g_perm[blockIdx.x];
        int L = lengths[b];
        if (L < 1) L = 1;
        if (L > T) L = T;
        const int m = L >> 1;
        const float* eb = emis + (size_t)b * T * KTAGS;

        unsigned long long EA[24], EB[24];
        {
            const float4* trA = (const float4*)(trans + rA * KTAGS);
            const float4* trB = (const float4*)(trans + rB * KTAGS);
#pragma unroll
            for (int q = 0; q < 12; q++) {
                float4 va = trA[q];
                EA[2 * q]     = pk2(ex2f(va.x * L2E), ex2f(va.y * L2E));
                EA[2 * q + 1] = pk2(ex2f(va.z * L2E), ex2f(va.w * L2E));
                float4 vb4 = trB[q];
                EB[2 * q]     = pk2(ex2f(vb4.x * L2E), ex2f(vb4.y * L2E));
                EB[2 * q + 1] = pk2(ex2f(vb4.z * L2E), ex2f(vb4.w * L2E));
            }
        }

        float aA = eb[rA] + prior[rA];
        float aB = eb[rB] + prior[rB];
        float m0 = __shfl_sync(0xffffffffu, aA, 0);
        float C2 = m0 * L2E;
        float wA = ex2f((aA - m0) * L2E);
        float wB = ex2f((aB - m0) * L2E);
        sv[0][rA] = wA;
        if (hB) sv[0][rB] = wB;
        __syncwarp();
        int p = 0;

        const int Lf = m + 1;   // consume t = 1..m
        float rawA[PF], rawB[PF];
#pragma unroll
        for (int d = 0; d < PF; d++) {
            int t = 1 + d;
            rawA[d] = (t < Lf) ? eb[(size_t)t * KTAGS + rA] : 0.0f;
            rawB[d] = (t < Lf) ? eb[(size_t)t * KTAGS + rB] : 0.0f;
        }

        int t0 = 1;
        // phase 1a: branch-free full blocks
        {
            const float* bA = eb + (size_t)(1 + PF) * KTAGS + rA;
            const float* bBp = eb + (size_t)(1 + PF) * KTAGS + rB;
            for (; t0 + 2 * PF <= Lf; t0 += PF) {
#pragma unroll
                for (int d = 0; d < PF; d++) {
                    float eetA = ex2f(rawA[d] * L2E);
                    float eetB = ex2f(rawB[d] * L2E);
                    rawA[d] = bA[d * KTAGS];
                    rawB[d] = bBp[d * KTAGS];

                    float gA = eetA, gB = eetB;
                    if ((d & 3) == 0) {
                        float r = __shfl_sync(0xffffffffu, wA, 0);
                        float rr = rcpf(r);
                        C2 += lg2f(r);
                        gA = eetA * rr;
                        gB = eetB * rr;
                    }

                    float uA, uB;
                    matvec48(EA, EB, sv[p], uA, uB);
                    wA = uA * gA;
                    wB = uB * gB;

                    const int q2 = p ^ 1;
                    sv[q2][rA] = wA;
                    if (hB) sv[q2][rB] = wB;
                    __syncwarp();
                    p = q2;
                }
                bA += PF * KTAGS;
                bBp += PF * KTAGS;
            }
        }
        // phase 1b: predicated tail
        for (; t0 < Lf; t0 += PF) {
#pragma unroll
            for (int d = 0; d < PF; d++) {
                const int t = t0 + d;
                if (t >= Lf) break;

                float eetA = ex2f(rawA[d] * L2E);
                float eetB = ex2f(rawB[d] * L2E);
                {
                    int tn = t + PF;
                    rawA[d] = (tn < Lf) ? eb[(size_t)tn * KTAGS + rA] : 0.0f;
                    rawB[d] = (tn < Lf) ? eb[(size_t)tn * KTAGS + rB] : 0.0f;
                }

                float gA = eetA, gB = eetB;
                if ((d & 3) == 0) {
                    float r = __shfl_sync(0xffffffffu, wA, 0);
                    float rr = rcpf(r);
                    C2 += lg2f(r);
                    gA = eetA * rr;
                    gB = eetB * rr;
                }

                float uA, uB;
                matvec48(EA, EB, sv[p], uA, uB);
                wA = uA * gA;
                wB = uB * gB;

                const int q2 = p ^ 1;
                sv[q2][rA] = wA;
                if (hB) sv[q2][rB] = wB;
                __syncwarp();
                p = q2;
            }
        }

        g_wf[b * KTAGS + rA] = wA;
        if (hB) g_wf[b * KTAGS + rB] = wB;
        if (j == 0) g_c2f[b] = C2;

        // path score over full L (this batch appears exactly once as forward)
        const int* tb = tags + (size_t)b * T;
        float acc = 0.0f;
        for (int t = j; t < L; t += 32) {
            int tg = min(max(tb[t], 0), KTAGS - 1);
            float tr = (t == 0) ? prior[tg]
                                : trans[tg * KTAGS + min(max(tb[t - 1], 0), KTAGS - 1)];
            acc += eb[(size_t)t * KTAGS + tg] + tr;
        }
#pragma unroll
        for (int s = 16; s > 0; s >>= 1)
            acc += __shfl_xor_sync(0xffffffffu, acc, s);
        if (j == 0)
            g_path[b] = acc + ftrans[min(max(tb[L - 1], 0), KTAGS - 1)];
    }

    // ================= phase 2: backward =================
    {
        const int b = g_perm[B - 1 - blockIdx.x];
        int L = lengths[b];
        if (L < 1) L = 1;
        if (L > T) L = T;
        const int m = L >> 1;
        const float* eb = emis + (size_t)b * T * KTAGS;

        unsigned long long EA[24], EB[24];
#pragma unroll
        for (int q = 0; q < 24; q++) {
            int j0 = 2 * q, j1 = 2 * q + 1;
            EA[q] = pk2(ex2f(trans[j0 * KTAGS + rA] * L2E),
                        ex2f(trans[j1 * KTAGS + rA] * L2E));
            EB[q] = pk2(ex2f(trans[j0 * KTAGS + rB] * L2E),
                        ex2f(trans[j1 * KTAGS + rB] * L2E));
        }

        float C2 = 0.0f;
        float vbA, vbB;

        if (m == L - 1) {
            vbA = ex2f(ftrans[rA] * L2E);
            vbB = ex2f(ftrans[rB] * L2E);
        } else {
            float zA = ex2f((ftrans[rA] + eb[(size_t)(L - 1) * KTAGS + rA]) * L2E);
            float zB = ex2f((ftrans[rB] + eb[(size_t)(L - 1) * KTAGS + rB]) * L2E);
            int p = 0;

            const int nsteps = L - 1 - m;
            const int nfull = nsteps - 1;

            float rawA[PF], rawB[PF];
#pragma unroll
            for (int d = 0; d < PF; d++) {
                int t = L - 2 - d;
                rawA[d] = (d < nfull) ? eb[(size_t)t * KTAGS + rA] : 0.0f;
                rawB[d] = (d < nfull) ? eb[(size_t)t * KTAGS + rB] : 0.0f;
            }

            int s0 = 0;
            // phase 2a: branch-free full blocks
            if (2 * PF <= nfull) {
                const float* bA = eb + (size_t)(L - 2 - PF) * KTAGS + rA;
                const float* bBp = eb + (size_t)(L - 2 - PF) * KTAGS + rB;
                for (; s0 + 2 * PF <= nfull; s0 += PF) {
#pragma unroll
                    for (int d = 0; d < PF; d++) {
                        float eetA = ex2f(rawA[d] * L2E);
                        float eetB = ex2f(rawB[d] * L2E);
                        rawA[d] = *(bA - d * KTAGS);
                        rawB[d] = *(bBp - d * KTAGS);

                        float gA = eetA, gB = eetB;
                        if ((d & 3) == 0) {
                            float r = __shfl_sync(0xffffffffu, zA, 0);
                            float rr = rcpf(r);
                            C2 += lg2f(r);
                            gA = eetA * rr;
                            gB = eetB * rr;
                        }

                        sv[p ^ 1][rA] = zA * gA;
                        if (hB) sv[p ^ 1][rB] = zB * gB;
                        __syncwarp();
                        float uA, uB;
                        matvec48(EA, EB, sv[p ^ 1], uA, uB);
                        zA = uA;
                        zB = uB;
                        p ^= 1;
                    }
                    bA -= PF * KTAGS;
                    bBp -= PF * KTAGS;
                }
            }
            // phase 2b: predicated tail
            for (; s0 < nfull; s0 += PF) {
#pragma unroll
                for (int d = 0; d < PF; d++) {
                    const int s = s0 + d;
                    if (s >= nfull) break;
                    const int t = L - 2 - s;

                    float eetA = ex2f(rawA[d] * L2E);
                    float eetB = ex2f(rawB[d] * L2E);
                    {
                        int sn = s + PF;
                        int tn = t - PF;
                        rawA[d] = (sn < nfull) ? eb[(size_t)tn * KTAGS + rA] : 0.0f;
                        rawB[d] = (sn < nfull) ? eb[(size_t)tn * KTAGS + rB] : 0.0f;
                    }

                    float gA = eetA, gB = eetB;
                    if ((d & 3) == 0) {
                        float r = __shfl_sync(0xffffffffu, zA, 0);
                        float rr = rcpf(r);
                        C2 += lg2f(r);
                        gA = eetA * rr;
                        gB = eetB * rr;
                    }

                    sv[p ^ 1][rA] = zA * gA;
                    if (hB) sv[p ^ 1][rB] = zB * gB;
                    __syncwarp();
                    float uA, uB;
                    matvec48(EA, EB, sv[p ^ 1], uA, uB);
                    zA = uA;
                    zB = uB;
                    p ^= 1;
                }
            }
            // final step (t = m): matvec only
            sv[p ^ 1][rA] = zA;
            if (hB) sv[p ^ 1][rB] = zB;
            __syncwarp();
            matvec48(EA, EB, sv[p ^ 1], vbA, vbB);
        }

        g_wb[b * KTAGS + rA] = vbA;
        if (hB) g_wb[b * KTAGS + rB] = vbB;
        if (j == 0) g_c2b[b] = C2;
    }
}

// Combine + final mean in one kernel (last-block pattern; counter self-resets
// so the kernel is deterministic across graph replays).
__global__ void crf_combine(float* __restrict__ out, int B) {
    __shared__ float sh[8];
    __shared__ int lastFlag;
    const int tid = threadIdx.x;
    const int wid = tid >> 5, j = tid & 31;
    const int gw = blockIdx.x * 8 + wid;
    float v = 0.0f;
    for (int b = gw; b < B; b += 256) {
        float d = g_wf[b * KTAGS + j] * g_wb[b * KTAGS + j];
        if (j < 16) d += g_wf[b * KTAGS + 32 + j] * g_wb[b * KTAGS + 32 + j];
#pragma unroll
        for (int s = 16; s > 0; s >>= 1) d += __shfl_xor_sync(0xffffffffu, d, s);
        if (j == 0)
            v += (lg2f(d) + g_c2f[b] + g_c2b[b]) * LN2 - g_path[b];
    }
    if (j == 0) sh[wid] = v;
    __syncthreads();
    if (tid == 0) {
        float s = 0.0f;
#pragma unroll
        for (int k = 0; k < 8; k++) s += sh[k];
        g_partial[blockIdx.x] = s;
        __threadfence();
        unsigned prev = atomicAdd(&g_done, 1u);
        lastFlag = (prev == 31u);
    }
    __syncthreads();
    if (lastFlag && tid < 32) {
        __threadfence();
        float v2 = g_partial[tid];
#pragma unroll
        for (int s = 16; s > 0; s >>= 1) v2 += __shfl_xor_sync(0xffffffffu, v2, s);
        if (tid == 0) {
            out[0] = v2 / (float)B;
            g_done = 0;   // reset for next graph replay
        }
    }
}

extern "C" void kernel_launch(void* const* d_in, const int* in_sizes, int n_in,
                              void* d_out, int out_size) {
    const float* emis    = (const float*)d_in[0];
    const int*   lengths = (const int*)d_in[1];
    const int*   tags    = (const int*)d_in[2];
    const float* prior   = (const float*)d_in[3];
    const float* trans   = (const float*)d_in[4];
    const float* ftrans  = (const float*)d_in[5];

    const int B = in_sizes[1];              // lengths count
    const int T = in_sizes[2] / B;          // tags = [B, T]

    crf_sort<<<1, 512>>>(lengths, B, T);
    crf_bidir<<<B, 32>>>(emis, lengths, tags, prior, trans, ftrans, B, T);
    crf_combine<<<32, 256>>>((float*)d_out, B);
}

// round 14
// speedup vs baseline: 2.3764x; 1.1102x over previous
#include <cuda_runtime.h>

#define KTAGS 48
#define PF 8
#define L2E 1.4426950408889634f
#define LN2 0.6931471805599453f

#define MAXB 4096
__device__ float g_wf[MAXB * KTAGS];
__device__ float g_wb[MAXB * KTAGS];
__device__ float g_c2f[MAXB];
__device__ float g_c2b[MAXB];
__device__ float g_path[MAXB];
__device__ float g_partial[64];
__device__ int   g_perm[MAXB];

__device__ __forceinline__ unsigned long long pk2(float lo, float hi) {
    unsigned long long r;
    asm("mov.b64 %0,{%1,%2};" : "=l"(r) : "f"(lo), "f"(hi));
    return r;
}
__device__ __forceinline__ void unpk2(unsigned long long v, float& a, float& b) {
    asm("mov.b64 {%0,%1},%2;" : "=f"(a), "=f"(b) : "l"(v));
}
__device__ __forceinline__ unsigned long long ffma2(unsigned long long a, unsigned long long b,
                                                    unsigned long long c) {
    unsigned long long d;
    asm("fma.rn.f32x2 %0,%1,%2,%3;" : "=l"(d) : "l"(a), "l"(b), "l"(c));
    return d;
}
__device__ __forceinline__ unsigned long long fadd2(unsigned long long a, unsigned long long b) {
    unsigned long long d;
    asm("add.rn.f32x2 %0,%1,%2;" : "=l"(d) : "l"(a), "l"(b));
    return d;
}
__device__ __forceinline__ float ex2f(float x) {
    float r; asm("ex2.approx.f32 %0,%1;" : "=f"(r) : "f"(x)); return r;
}
__device__ __forceinline__ float lg2f(float x) {
    float r; asm("lg2.approx.f32 %0,%1;" : "=f"(r) : "f"(x)); return r;
}
__device__ __forceinline__ float rcpf(float x) {
    float r; asm("rcp.approx.f32 %0,%1;" : "=f"(r) : "f"(x)); return r;
}

// Lane j: full dot for row j (EA, 24 ffma2) + HALF dot for row 32+(j>>1)
// (EC, 12 ffma2; element range picked by lane parity via the vc address),
// combined across the lane pair with one shfl_xor. 36 ffma2 total.
__device__ __forceinline__ void matvec48b(const unsigned long long* EA,
                                          const unsigned long long* EC,
                                          const float* svp, int coff,
                                          float& outA, float& outC) {
    const ulonglong2* vv = (const ulonglong2*)svp;
    const ulonglong2* vc = (const ulonglong2*)(svp + coff);
    unsigned long long z = pk2(0.0f, 0.0f);
    unsigned long long a0 = z, a1 = z, a2 = z, a3 = z, c0 = z, c1 = z;
#pragma unroll
    for (int q = 0; q < 6; q++) {
        ulonglong2 xe = vv[q];
        ulonglong2 xo = vv[q + 6];
        ulonglong2 xc = vc[q];
        a0 = ffma2(EA[2 * q],      xe.x, a0);
        a1 = ffma2(EA[2 * q + 1],  xe.y, a1);
        a2 = ffma2(EA[2 * q + 12], xo.x, a2);
        a3 = ffma2(EA[2 * q + 13], xo.y, a3);
        c0 = ffma2(EC[2 * q],      xc.x, c0);
        c1 = ffma2(EC[2 * q + 1],  xc.y, c1);
    }
    unsigned long long sA = fadd2(fadd2(a0, a1), fadd2(a2, a3));
    unsigned long long sC = fadd2(c0, c1);
    float lo, hi;
    unpk2(sA, lo, hi); outA = lo + hi;
    unpk2(sC, lo, hi);
    float pc = lo + hi;
    pc += __shfl_xor_sync(0xffffffffu, pc, 1);
    outC = pc;
}

// Parallel rank (replaces bitonic sort): rank b = #{k: L_k>L_b || (== && k<b)}.
// Deterministic unique ranks; g_perm[rank] = b. Warp per batch element.
__global__ void crf_rank(const int* __restrict__ lengths, int B, int T) {
    __shared__ int sl[1024];
    for (int k = threadIdx.x; k < B; k += blockDim.x) {
        int L = lengths[k];
        sl[k] = L < 1 ? 1 : (L > T ? T : L);
    }
    __syncthreads();
    const int lane = threadIdx.x & 31;
    const int nw = (gridDim.x * blockDim.x) >> 5;
    for (int b = (blockIdx.x * blockDim.x + threadIdx.x) >> 5; b < B; b += nw) {
        int Lb = sl[b];
        int cnt = 0;
        for (int k = lane; k < B; k += 32) {
            int Lk = sl[k];
            cnt += (Lk > Lb) || (Lk == Lb && k < b);
        }
#pragma unroll
        for (int s = 16; s > 0; s >>= 1) cnt += __shfl_xor_sync(0xffffffffu, cnt, s);
        if (lane == 0) g_perm[cnt] = b;
    }
}

// Makespan-balanced bidirectional CRF: CTA i runs forward alpha 0..m of batch
// perm[i], then backward beta L-1..m of batch perm[B-1-i]; L_i + L_{B-1-i} ~
// const after ranking, so all CTAs do ~T/2 serial steps at 512 CTAs.
__global__ void __launch_bounds__(32) crf_bidir(
    const float* __restrict__ emis,   // [B, T, K]
    const int* __restrict__ lengths,  // [B]
    const int* __restrict__ tags,     // [B, T]
    const float* __restrict__ prior,  // [K]
    const float* __restrict__ trans,  // [K, K]
    const float* __restrict__ ftrans, // [K]
    int B, int T)
{
    __shared__ __align__(16) float sv[2][KTAGS];

    const int j = threadIdx.x;
    const int rA = j;
    const int rC = 32 + (j >> 1);
    const bool even = (j & 1) == 0;
    const int cbase = (j & 1) ? 24 : 0;   // element range of the half-row

    // ================= phase 1: forward =================
    {
        const int b = g_perm[blockIdx.x];
        int L = lengths[b];
        if (L < 1) L = 1;
        if (L > T) L = T;
        const int m = L >> 1;
        const float* eb = emis + (size_t)b * T * KTAGS;

        unsigned long long EA[24], EC[12];
        {
            const float4* trA = (const float4*)(trans + rA * KTAGS);
#pragma unroll
            for (int q = 0; q < 12; q++) {
                float4 va = trA[q];
                EA[2 * q]     = pk2(ex2f(va.x * L2E), ex2f(va.y * L2E));
                EA[2 * q + 1] = pk2(ex2f(va.z * L2E), ex2f(va.w * L2E));
            }
            const float* trC = trans + rC * KTAGS + cbase;
#pragma unroll
            for (int q = 0; q < 12; q++)
                EC[q] = pk2(ex2f(trC[2 * q] * L2E), ex2f(trC[2 * q + 1] * L2E));
        }

        float aA = eb[rA] + prior[rA];
        float aC = eb[rC] + prior[rC];
        float m0 = __shfl_sync(0xffffffffu, aA, 0);
        float C2 = m0 * L2E;
        float wA = ex2f((aA - m0) * L2E);
        float wC = ex2f((aC - m0) * L2E);
        sv[0][rA] = wA;
        if (even) sv[0][rC] = wC;
        __syncwarp();
        int p = 0;

        const int Lf = m + 1;   // consume t = 1..m
        float rawA[PF], rawC[PF];
#pragma unroll
        for (int d = 0; d < PF; d++) {
            int t = 1 + d;
            rawA[d] = (t < Lf) ? eb[(size_t)t * KTAGS + rA] : 0.0f;
            rawC[d] = (t < Lf) ? eb[(size_t)t * KTAGS + rC] : 0.0f;
        }

        int t0 = 1;
        // phase 1a: branch-free full blocks
        {
            const float* bA = eb + (size_t)(1 + PF) * KTAGS + rA;
            const float* bC = eb + (size_t)(1 + PF) * KTAGS + rC;
            for (; t0 + 2 * PF <= Lf; t0 += PF) {
#pragma unroll
                for (int d = 0; d < PF; d++) {
                    float eetA = ex2f(rawA[d] * L2E);
                    float eetC = ex2f(rawC[d] * L2E);
                    rawA[d] = bA[d * KTAGS];
                    rawC[d] = bC[d * KTAGS];

                    float gA = eetA, gC = eetC;
                    if ((d & 3) == 0) {
                        float r = __shfl_sync(0xffffffffu, wA, 0);
                        float rr = rcpf(r);
                        C2 += lg2f(r);
                        gA = eetA * rr;
                        gC = eetC * rr;
                    }

                    float uA, uC;
                    matvec48b(EA, EC, sv[p], cbase, uA, uC);
                    wA = uA * gA;
                    wC = uC * gC;

                    const int q2 = p ^ 1;
                    sv[q2][rA] = wA;
                    if (even) sv[q2][rC] = wC;
                    __syncwarp();
                    p = q2;
                }
                bA += PF * KTAGS;
                bC += PF * KTAGS;
            }
        }
        // phase 1b: predicated tail
        for (; t0 < Lf; t0 += PF) {
#pragma unroll
            for (int d = 0; d < PF; d++) {
                const int t = t0 + d;
                if (t >= Lf) break;

                float eetA = ex2f(rawA[d] * L2E);
                float eetC = ex2f(rawC[d] * L2E);
                {
                    int tn = t + PF;
                    rawA[d] = (tn < Lf) ? eb[(size_t)tn * KTAGS + rA] : 0.0f;
                    rawC[d] = (tn < Lf) ? eb[(size_t)tn * KTAGS + rC] : 0.0f;
                }

                float gA = eetA, gC = eetC;
                if ((d & 3) == 0) {
                    float r = __shfl_sync(0xffffffffu, wA, 0);
                    float rr = rcpf(r);
                    C2 += lg2f(r);
                    gA = eetA * rr;
                    gC = eetC * rr;
                }

                float uA, uC;
                matvec48b(EA, EC, sv[p], cbase, uA, uC);
                wA = uA * gA;
                wC = uC * gC;

                const int q2 = p ^ 1;
                sv[q2][rA] = wA;
                if (even) sv[q2][rC] = wC;
                __syncwarp();
                p = q2;
            }
        }

        g_wf[b * KTAGS + rA] = wA;
        if (even) g_wf[b * KTAGS + rC] = wC;
        if (j == 0) g_c2f[b] = C2;

        // path score over full L
        const int* tb = tags + (size_t)b * T;
        float acc = 0.0f;
        for (int t = j; t < L; t += 32) {
            int tg = min(max(tb[t], 0), KTAGS - 1);
            float tr = (t == 0) ? prior[tg]
                                : trans[tg * KTAGS + min(max(tb[t - 1], 0), KTAGS - 1)];
            acc += eb[(size_t)t * KTAGS + tg] + tr;
        }
#pragma unroll
        for (int s = 16; s > 0; s >>= 1)
            acc += __shfl_xor_sync(0xffffffffu, acc, s);
        if (j == 0)
            g_path[b] = acc + ftrans[min(max(tb[L - 1], 0), KTAGS - 1)];
    }

    // ================= phase 2: backward =================
    {
        const int b = g_perm[B - 1 - blockIdx.x];
        int L = lengths[b];
        if (L < 1) L = 1;
        if (L > T) L = T;
        const int m = L >> 1;
        const float* eb = emis + (size_t)b * T * KTAGS;

        unsigned long long EA[24], EC[12];
#pragma unroll
        for (int q = 0; q < 24; q++) {
            int j0 = 2 * q, j1 = 2 * q + 1;
            EA[q] = pk2(ex2f(trans[j0 * KTAGS + rA] * L2E),
                        ex2f(trans[j1 * KTAGS + rA] * L2E));
        }
#pragma unroll
        for (int q = 0; q < 12; q++) {
            int j0 = cbase + 2 * q, j1 = cbase + 2 * q + 1;
            EC[q] = pk2(ex2f(trans[j0 * KTAGS + rC] * L2E),
                        ex2f(trans[j1 * KTAGS + rC] * L2E));
        }

        float C2 = 0.0f;
        float vbA, vbC;

        if (m == L - 1) {
            vbA = ex2f(ftrans[rA] * L2E);
            vbC = ex2f(ftrans[rC] * L2E);
        } else {
            float zA = ex2f((ftrans[rA] + eb[(size_t)(L - 1) * KTAGS + rA]) * L2E);
            float zC = ex2f((ftrans[rC] + eb[(size_t)(L - 1) * KTAGS + rC]) * L2E);
            int p = 0;

            const int nsteps = L - 1 - m;
            const int nfull = nsteps - 1;

            float rawA[PF], rawC[PF];
#pragma unroll
            for (int d = 0; d < PF; d++) {
                int t = L - 2 - d;
                rawA[d] = (d < nfull) ? eb[(size_t)t * KTAGS + rA] : 0.0f;
                rawC[d] = (d < nfull) ? eb[(size_t)t * KTAGS + rC] : 0.0f;
            }

            int s0 = 0;
            // phase 2a: branch-free full blocks
            if (2 * PF <= nfull) {
                const float* bA = eb + (size_t)(L - 2 - PF) * KTAGS + rA;
                const float* bC = eb + (size_t)(L - 2 - PF) * KTAGS + rC;
                for (; s0 + 2 * PF <= nfull; s0 += PF) {
#pragma unroll
                    for (int d = 0; d < PF; d++) {
                        float eetA = ex2f(rawA[d] * L2E);
                        float eetC = ex2f(rawC[d] * L2E);
                        rawA[d] = *(bA - d * KTAGS);
                        rawC[d] = *(bC - d * KTAGS);

                        float gA = eetA, gC = eetC;
                        if ((d & 3) == 0) {
                            float r = __shfl_sync(0xffffffffu, zA, 0);
                            float rr = rcpf(r);
                            C2 += lg2f(r);
                            gA = eetA * rr;
                            gC = eetC * rr;
                        }

                        const int pn = p ^ 1;
                        sv[pn][rA] = zA * gA;
                        if (even) sv[pn][rC] = zC * gC;
                        __syncwarp();
                        float uA, uC;
                        matvec48b(EA, EC, sv[pn], cbase, uA, uC);
                        zA = uA;
                        zC = uC;
                        p = pn;
                    }
                    bA -= PF * KTAGS;
                    bC -= PF * KTAGS;
                }
            }
            // phase 2b: predicated tail
            for (; s0 < nfull; s0 += PF) {
#pragma unroll
                for (int d = 0; d < PF; d++) {
                    const int s = s0 + d;
                    if (s >= nfull) break;
                    const int t = L - 2 - s;

                    float eetA = ex2f(rawA[d] * L2E);
                    float eetC = ex2f(rawC[d] * L2E);
                    {
                        int sn = s + PF;
                        int tn = t - PF;
                        rawA[d] = (sn < nfull) ? eb[(size_t)tn * KTAGS + rA] : 0.0f;
                        rawC[d] = (sn < nfull) ? eb[(size_t)tn * KTAGS + rC] : 0.0f;
                    }

                    float gA = eetA, gC = eetC;
                    if ((d & 3) == 0) {
                        float r = __shfl_sync(0xffffffffu, zA, 0);
                        float rr = rcpf(r);
                        C2 += lg2f(r);
                        gA = eetA * rr;
                        gC = eetC * rr;
                    }

                    const int pn = p ^ 1;
                    sv[pn][rA] = zA * gA;
                    if (even) sv[pn][rC] = zC * gC;
                    __syncwarp();
                    float uA, uC;
                    matvec48b(EA, EC, sv[pn], cbase, uA, uC);
                    zA = uA;
                    zC = uC;
                    p = pn;
                }
            }
            // final step (t = m): matvec only
            const int pn = p ^ 1;
            sv[pn][rA] = zA;
            if (even) sv[pn][rC] = zC;
            __syncwarp();
            matvec48b(EA, EC, sv[pn], cbase, vbA, vbC);
        }

        g_wb[b * KTAGS + rA] = vbA;
        if (even) g_wb[b * KTAGS + rC] = vbC;
        if (j == 0) g_c2b[b] = C2;
    }
}

// Parallel combine: 32 blocks x 256 threads, one warp per batch iteration.
__global__ void crf_combine(int B) {
    __shared__ float sh[8];
    const int tid = threadIdx.x;
    const int wid = tid >> 5, j = tid & 31;
    const int gw = blockIdx.x * 8 + wid;
    float v = 0.0f;
    for (int b = gw; b < B; b += 256) {
        float d = g_wf[b * KTAGS + j] * g_wb[b * KTAGS + j];
        if (j < 16) d += g_wf[b * KTAGS + 32 + j] * g_wb[b * KTAGS + 32 + j];
#pragma unroll
        for (int s = 16; s > 0; s >>= 1) d += __shfl_xor_sync(0xffffffffu, d, s);
        if (j == 0)
            v += (lg2f(d) + g_c2f[b] + g_c2b[b]) * LN2 - g_path[b];
    }
    if (j == 0) sh[wid] = v;
    __syncthreads();
    if (tid == 0) {
        float s = 0.0f;
#pragma unroll
        for (int k = 0; k < 8; k++) s += sh[k];
        g_partial[blockIdx.x] = s;
    }
}

__global__ void crf_final(float* __restrict__ out, int B) {
    const int j = threadIdx.x;
    float v = g_partial[j];
#pragma unroll
    for (int s = 16; s > 0; s >>= 1) v += __shfl_xor_sync(0xffffffffu, v, s);
    if (j == 0) out[0] = v / (float)B;
}

extern "C" void kernel_launch(void* const* d_in, const int* in_sizes, int n_in,
                              void* d_out, int out_size) {
    const float* emis    = (const float*)d_in[0];
    const int*   lengths = (const int*)d_in[1];
    const int*   tags    = (const int*)d_in[2];
    const float* prior   = (const float*)d_in[3];
    const float* trans   = (const float*)d_in[4];
    const float* ftrans  = (const float*)d_in[5];

    const int B = in_sizes[1];              // lengths count
    const int T = in_sizes[2] / B;          // tags = [B, T]

    crf_rank<<<16, 256>>>(lengths, B, T);
    crf_bidir<<<B, 32>>>(emis, lengths, tags, prior, trans, ftrans, B, T);
    crf_combine<<<32, 256>>>(B);
    crf_final<<<1, 32>>>((float*)d_out, B);
}